// round 14
// baseline (speedup 1.0000x reference)
#include <cuda_runtime.h>
#include <cuda_bf16.h>
#include <cuda_fp16.h>
#include <math.h>
#include <stdint.h>

#define NT 8192
#define NS 8192
#define FD 128
#define KSEL 2457
#define BN_EPS 1e-5f
#define INV_TAU (1.0f/0.07f)
#define QSCALE (INV_TAU * 2048.0f)
#define INV2048 4.8828125e-4f
#define KEYSPACE (2*64*128*128)

// ---------------- scratch (device globals) --------------------------------------------
__device__ __align__(16) float g_h2[2][NS*FD];
__device__ __align__(16) unsigned short g_simsq[(size_t)NS*NT];  // 128MB
__device__ __align__(16) __half g_Ah[NS*FD];   // student projections, fp16
__device__ __align__(16) __half g_Bh[NT*FD];   // teacher projections, fp16
__device__ __align__(16) uint4 g_wq[2][2][2][2048];  // [net][layer][hi/lo] swizzled bf16 chunks
__device__ int   g_keymap[KEYSPACE];   // 0 = empty; restored by k_fin each launch
__device__ int   g_matched[NS];
__device__ int   g_tidx[NS];
__device__ int   g_cnt;
__device__ int   g_tile;               // fused work-queue counter
__device__ int   g_ready[64];          // per row-block completed-tile counters
__device__ float g_accum;
__device__ float g_bn_sum[2][FD];
__device__ float g_bn_sq[2][FD];

// ---------------- helpers ---------------------------------------------------------------
__device__ __forceinline__ uint32_t smem_to_u32(const void* p) {
    uint32_t a;
    asm("{ .reg .u64 t; cvta.to.shared.u64 t, %1; cvt.u32.u64 %0, t; }" : "=r"(a) : "l"(p));
    return a;
}
__device__ __forceinline__ void cp16(uint32_t s, const void* g) {
    asm volatile("cp.async.cg.shared.global [%0], [%1], 16;" :: "r"(s), "l"(g));
}
__device__ __forceinline__ void cp_commit_wait() {
    asm volatile("cp.async.commit_group;");
    asm volatile("cp.async.wait_group 0;");
}
__device__ __forceinline__ void ldm_x4(uint32_t* r, uint32_t addr) {
    asm volatile("ldmatrix.sync.aligned.m8n8.x4.shared.b16 {%0,%1,%2,%3}, [%4];"
        : "=r"(r[0]), "=r"(r[1]), "=r"(r[2]), "=r"(r[3]) : "r"(addr));
}
__device__ __forceinline__ void ldm_x2(uint32_t* r, uint32_t addr) {
    asm volatile("ldmatrix.sync.aligned.m8n8.x2.shared.b16 {%0,%1}, [%2];"
        : "=r"(r[0]), "=r"(r[1]) : "r"(addr));
}
__device__ __forceinline__ void mma_bf16(float* c, const uint32_t* a, const uint32_t* b) {
    asm volatile("mma.sync.aligned.m16n8k16.row.col.f32.bf16.bf16.f32 "
        "{%0,%1,%2,%3}, {%4,%5,%6,%7}, {%8,%9}, {%0,%1,%2,%3};"
        : "+f"(c[0]), "+f"(c[1]), "+f"(c[2]), "+f"(c[3])
        : "r"(a[0]), "r"(a[1]), "r"(a[2]), "r"(a[3]), "r"(b[0]), "r"(b[1]));
}
// fp16-accumulator MMA: D(half2 x2) = A*B + C
__device__ __forceinline__ void mma_f16acc(uint32_t* c, const uint32_t* a, const uint32_t* b) {
    asm volatile("mma.sync.aligned.m16n8k16.row.col.f16.f16.f16.f16 "
        "{%0,%1}, {%2,%3,%4,%5}, {%6,%7}, {%0,%1};"
        : "+r"(c[0]), "+r"(c[1])
        : "r"(a[0]), "r"(a[1]), "r"(a[2]), "r"(a[3]), "r"(b[0]), "r"(b[1]));
}
__device__ __forceinline__ float fexp(float x) {
    float y = x * 1.44269504088896340736f;
    float n = rintf(y);
    float t = (y - n) * 0.69314718055994530942f;
    float p = 1.0f/720.0f;
    p = fmaf(p, t, 1.0f/120.0f);
    p = fmaf(p, t, 1.0f/24.0f);
    p = fmaf(p, t, 1.0f/6.0f);
    p = fmaf(p, t, 0.5f);
    p = fmaf(p, t, 1.0f);
    p = fmaf(p, t, 1.0f);
    int ni = (int)n;
    return p * __int_as_float((ni + 127) << 23);
}
__device__ __forceinline__ uint32_t pack_hi(float a, float b) {
    __nv_bfloat16 h0 = __float2bfloat16(a), h1 = __float2bfloat16(b);
    return (uint32_t)__bfloat16_as_ushort(h0) | ((uint32_t)__bfloat16_as_ushort(h1) << 16);
}
__device__ __forceinline__ uint32_t pack_lo(float a, float b) {
    __nv_bfloat16 h0 = __float2bfloat16(a), h1 = __float2bfloat16(b);
    float r0 = a - __bfloat162float(h0), r1 = b - __bfloat162float(h1);
    __nv_bfloat16 l0 = __float2bfloat16(r0), l1 = __float2bfloat16(r1);
    return (uint32_t)__bfloat16_as_ushort(l0) | ((uint32_t)__bfloat16_as_ushort(l1) << 16);
}

// ---------------- prep: scatter keys + clears + weight transpose/split -------------------
__global__ void k_prep(const int* __restrict__ tc,
                       const float* __restrict__ tw1, const float* __restrict__ tw2,
                       const float* __restrict__ sw1, const float* __restrict__ sw2) {
    int i = blockIdx.x * 256 + threadIdx.x;
    int4 c = ((const int4*)tc)[i];
    int key = ((c.x * 64 + c.y) * 128 + c.z) * 128 + c.w;
    g_keymap[key] = i + 1;
    g_matched[i] = 0;
    if (i < 2*FD) {
        ((float*)g_bn_sum)[i] = 0.f;
        ((float*)g_bn_sq)[i]  = 0.f;
    }
    if (i < 64) g_ready[i] = 0;
    if (i == 0) { g_cnt = 0; g_accum = 0.f; g_tile = 0; }

    if (i < 4096) {
        int kg = i & 7, n = (i >> 3) & 127, layer = (i >> 10) & 1, net = i >> 11;
        const float* w = net ? (layer ? sw2 : sw1) : (layer ? tw2 : tw1);
        #pragma unroll
        for (int half = 0; half < 2; half++) {
            int kb = kg * 16 + half * 8;
            uint32_t hw[4], lw[4];
            #pragma unroll
            for (int q = 0; q < 4; q++) {
                float v0 = w[(kb + q*2    ) * 128 + n];
                float v1 = w[(kb + q*2 + 1) * 128 + n];
                hw[q] = pack_hi(v0, v1);
                lw[q] = pack_lo(v0, v1);
            }
            int ch = kg * 2 + half;
            int idx = n * 16 + (ch ^ (n & 7));
            g_wq[net][layer][0][idx] = make_uint4(hw[0], hw[1], hw[2], hw[3]);
            g_wq[net][layer][1][idx] = make_uint4(lw[0], lw[1], lw[2], lw[3]);
        }
    }
}

// ---------------- fused 2-layer projection via HMMA hi/lo (+ distributed match) ----------
#define PJ_XH 0
#define PJ_XL 32768
#define PJ_W1H 65536
#define PJ_W1L 98304
#define PJ_W2H 131072
#define PJ_W2L 163840
#define PJ_BIAS 196608
#define PJ_CS 197632
#define PJ_CQ 198144
#define SM_PROJ 198656

__global__ __launch_bounds__(256) void k_projmma(
    const float* __restrict__ tf, const float* __restrict__ sf,
    const float* __restrict__ tb1, const float* __restrict__ tb2,
    const float* __restrict__ sb1, const float* __restrict__ sb2,
    const int* __restrict__ sco)
{
    extern __shared__ char smc[];
    uint32_t sb = smem_to_u32(smc);
    float* smf = (float*)smc;
    int net = blockIdx.z;
    const float* x  = net ? sf : tf;
    const float* b1 = net ? sb1 : tb1;
    const float* b2 = net ? sb2 : tb2;
    int tid = threadIdx.x;
    int r0 = blockIdx.x * 128;

    // distributed coordinate matching: 64 student rows per CTA (128 CTAs total)
    if (tid < 64) {
        int j0 = (net * 64 + blockIdx.x) * 64 + tid;
        int4 c = ((const int4*)sco)[j0];
        int key = ((c.x * 64 + c.y) * 128 + c.z) * 128 + c.w;
        int t = g_keymap[key] - 1;
        g_tidx[j0] = (t < 0) ? 0 : t;
        unsigned m = __ballot_sync(0xffffffffu, t >= 0);
        int base = 0;
        if ((tid & 31) == 0) base = atomicAdd(&g_cnt, __popc(m));
        base = __shfl_sync(0xffffffffu, base, 0);
        if (t >= 0) {
            int rank = __popc(m & ((1u << (tid & 31)) - 1u));
            g_matched[base + rank] = j0;
        }
    }

    // load X fp32 -> hi/lo bf16 swizzled smem
    #pragma unroll
    for (int it = 0; it < 8; it++) {
        int cidx = tid + it * 256;
        int row = cidx >> 4, ch = cidx & 15;
        const float4* src = (const float4*)(x + (size_t)(r0 + row) * FD + ch * 8);
        float4 f0 = src[0], f1 = src[1];
        uint4 hv, lv;
        hv.x = pack_hi(f0.x, f0.y); lv.x = pack_lo(f0.x, f0.y);
        hv.y = pack_hi(f0.z, f0.w); lv.y = pack_lo(f0.z, f0.w);
        hv.z = pack_hi(f1.x, f1.y); lv.z = pack_lo(f1.x, f1.y);
        hv.w = pack_hi(f1.z, f1.w); lv.w = pack_lo(f1.z, f1.w);
        uint32_t off = (uint32_t)row * 256 + (uint32_t)((ch ^ (row & 7)) << 4);
        *(uint4*)(smc + PJ_XH + off) = hv;
        *(uint4*)(smc + PJ_XL + off) = lv;
    }
    #pragma unroll
    for (int it = 0; it < 8; it++) {
        int cidx = tid + it * 256;
        ((uint4*)(smc + PJ_W1H))[cidx] = g_wq[net][0][0][cidx];
        ((uint4*)(smc + PJ_W1L))[cidx] = g_wq[net][0][1][cidx];
        ((uint4*)(smc + PJ_W2H))[cidx] = g_wq[net][1][0][cidx];
        ((uint4*)(smc + PJ_W2L))[cidx] = g_wq[net][1][1][cidx];
    }
    if (tid < 128) {
        smf[PJ_BIAS/4 + tid]       = b1[tid];
        smf[PJ_BIAS/4 + 128 + tid] = b2[tid];
        smf[PJ_CS/4 + tid] = 0.f;
        smf[PJ_CQ/4 + tid] = 0.f;
    }
    __syncthreads();

    int lane = tid & 31, wid = tid >> 5;
    int wm = wid >> 2, wn = wid & 3;
    int a_sub   = lane >> 3;
    int a_rowin = (lane & 7) + ((a_sub & 1) << 3);
    int a_cb    = a_sub >> 1;
    int b_rowin = lane & 7;
    int b_cb    = (lane >> 3) & 1;
    int g = lane >> 2, t = lane & 3;

    uint32_t aBase[4], bBase[4];
    int aM7[4], bM7[4];
    #pragma unroll
    for (int i = 0; i < 4; i++) {
        int row = wm * 64 + i * 16 + a_rowin;
        aBase[i] = sb + PJ_XH + row * 256;
        aM7[i] = row & 7;
        int rn = wn * 32 + i * 8 + b_rowin;
        bBase[i] = sb + rn * 256;
        bM7[i] = rn & 7;
    }

    float acc[4][4][4];

    // ---- layer 1 ----
    #pragma unroll
    for (int i = 0; i < 4; i++)
        #pragma unroll
        for (int j = 0; j < 4; j++)
            #pragma unroll
            for (int q = 0; q < 4; q++) acc[i][j][q] = 0.f;
    #pragma unroll
    for (int ks = 0; ks < 8; ks++) {
        int k2 = ks * 2;
        uint32_t aH[4][4], aL[4][4], bH[4][2], bL[4][2];
        #pragma unroll
        for (int i = 0; i < 4; i++) {
            uint32_t ad = aBase[i] + (((k2 + a_cb) ^ aM7[i]) << 4);
            ldm_x4(aH[i], ad);
            ldm_x4(aL[i], ad + 32768);
        }
        #pragma unroll
        for (int j = 0; j < 4; j++) {
            uint32_t bd = bBase[j] + PJ_W1H + (((k2 + b_cb) ^ bM7[j]) << 4);
            ldm_x2(bH[j], bd);
            ldm_x2(bL[j], bd + 32768);
        }
        #pragma unroll
        for (int i = 0; i < 4; i++)
            #pragma unroll
            for (int j = 0; j < 4; j++) {
                mma_bf16(acc[i][j], aH[i], bH[j]);
                mma_bf16(acc[i][j], aH[i], bL[j]);
                mma_bf16(acc[i][j], aL[i], bH[j]);
            }
    }
    __syncthreads();

    // bias + relu + re-split into XH/XL (now H1)
    #pragma unroll
    for (int i = 0; i < 4; i++) {
        #pragma unroll
        for (int j = 0; j < 4; j++) {
            int col0 = wn * 32 + j * 8 + t * 2;
            float bb0 = smf[PJ_BIAS/4 + col0], bb1 = smf[PJ_BIAS/4 + col0 + 1];
            float v0 = fmaxf(acc[i][j][0] + bb0, 0.f);
            float v1 = fmaxf(acc[i][j][1] + bb1, 0.f);
            float v2 = fmaxf(acc[i][j][2] + bb0, 0.f);
            float v3 = fmaxf(acc[i][j][3] + bb1, 0.f);
            int rl = wm * 64 + i * 16 + g, rh = rl + 8;
            uint32_t offl = rl * 256 + (((col0 >> 3) ^ (rl & 7)) << 4) + (col0 & 7) * 2;
            uint32_t offh = rh * 256 + (((col0 >> 3) ^ (rh & 7)) << 4) + (col0 & 7) * 2;
            *(uint32_t*)(smc + PJ_XH + offl) = pack_hi(v0, v1);
            *(uint32_t*)(smc + PJ_XL + offl) = pack_lo(v0, v1);
            *(uint32_t*)(smc + PJ_XH + offh) = pack_hi(v2, v3);
            *(uint32_t*)(smc + PJ_XL + offh) = pack_lo(v2, v3);
        }
    }
    __syncthreads();

    // ---- layer 2 ----
    #pragma unroll
    for (int i = 0; i < 4; i++)
        #pragma unroll
        for (int j = 0; j < 4; j++)
            #pragma unroll
            for (int q = 0; q < 4; q++) acc[i][j][q] = 0.f;
    #pragma unroll
    for (int ks = 0; ks < 8; ks++) {
        int k2 = ks * 2;
        uint32_t aH[4][4], aL[4][4], bH[4][2], bL[4][2];
        #pragma unroll
        for (int i = 0; i < 4; i++) {
            uint32_t ad = aBase[i] + (((k2 + a_cb) ^ aM7[i]) << 4);
            ldm_x4(aH[i], ad);
            ldm_x4(aL[i], ad + 32768);
        }
        #pragma unroll
        for (int j = 0; j < 4; j++) {
            uint32_t bd = bBase[j] + PJ_W2H + (((k2 + b_cb) ^ bM7[j]) << 4);
            ldm_x2(bH[j], bd);
            ldm_x2(bL[j], bd + 32768);
        }
        #pragma unroll
        for (int i = 0; i < 4; i++)
            #pragma unroll
            for (int j = 0; j < 4; j++) {
                mma_bf16(acc[i][j], aH[i], bH[j]);
                mma_bf16(acc[i][j], aH[i], bL[j]);
                mma_bf16(acc[i][j], aL[i], bH[j]);
            }
    }

    float* out = g_h2[net];
    #pragma unroll
    for (int j = 0; j < 4; j++) {
        int col0 = wn * 32 + j * 8 + t * 2;
        float bb0 = smf[PJ_BIAS/4 + 128 + col0], bb1 = smf[PJ_BIAS/4 + 128 + col0 + 1];
        float s0 = 0.f, q0 = 0.f, s1 = 0.f, q1 = 0.f;
        #pragma unroll
        for (int i = 0; i < 4; i++) {
            float v0 = acc[i][j][0] + bb0;
            float v1 = acc[i][j][1] + bb1;
            float v2 = acc[i][j][2] + bb0;
            float v3 = acc[i][j][3] + bb1;
            int rl = wm * 64 + i * 16 + g, rh = rl + 8;
            *(float2*)&out[(size_t)(r0 + rl) * FD + col0] = make_float2(v0, v1);
            *(float2*)&out[(size_t)(r0 + rh) * FD + col0] = make_float2(v2, v3);
            s0 += v0 + v2; q0 += v0*v0 + v2*v2;
            s1 += v1 + v3; q1 += v1*v1 + v3*v3;
        }
        atomicAdd(&smf[PJ_CS/4 + col0], s0);
        atomicAdd(&smf[PJ_CQ/4 + col0], q0);
        atomicAdd(&smf[PJ_CS/4 + col0 + 1], s1);
        atomicAdd(&smf[PJ_CQ/4 + col0 + 1], q1);
    }
    __syncthreads();
    if (tid < 128) {
        atomicAdd(&g_bn_sum[net][tid], smf[PJ_CS/4 + tid]);
        atomicAdd(&g_bn_sq[net][tid],  smf[PJ_CQ/4 + tid]);
    }
}

// ---------------- fused BNfinal + BN apply + L2 normalize + fp16 convert ------------------
__global__ void k_normsplit(const float* __restrict__ tg, const float* __restrict__ tbe,
                            const float* __restrict__ sg, const float* __restrict__ sbe) {
    int net = blockIdx.z;
    const float* h = g_h2[net];
    const float* gam = net ? sg : tg;
    const float* bet = net ? sbe : tbe;
    __half* dst = net ? g_Ah : g_Bh;
    int w = threadIdx.x >> 5, l = threadIdx.x & 31;
    int r = blockIdx.x * 8 + w;

    float4 su = *(const float4*)&g_bn_sum[net][l*4];
    float4 sq = *(const float4*)&g_bn_sq[net][l*4];
    float4 gm = *(const float4*)&gam[l*4];
    float4 bt = *(const float4*)&bet[l*4];
    float sc[4], sh[4];
    {
        float mu, var;
        mu = su.x*(1.f/8192.f); var = sq.x*(1.f/8192.f) - mu*mu;
        sc[0] = rsqrtf(var + BN_EPS) * gm.x; sh[0] = bt.x - mu * sc[0];
        mu = su.y*(1.f/8192.f); var = sq.y*(1.f/8192.f) - mu*mu;
        sc[1] = rsqrtf(var + BN_EPS) * gm.y; sh[1] = bt.y - mu * sc[1];
        mu = su.z*(1.f/8192.f); var = sq.z*(1.f/8192.f) - mu*mu;
        sc[2] = rsqrtf(var + BN_EPS) * gm.z; sh[2] = bt.z - mu * sc[2];
        mu = su.w*(1.f/8192.f); var = sq.w*(1.f/8192.f) - mu*mu;
        sc[3] = rsqrtf(var + BN_EPS) * gm.w; sh[3] = bt.w - mu * sc[3];
    }
    float4 v = *(const float4*)&h[(size_t)r*FD + l*4];
    float y[4];
    y[0] = fmaf(v.x, sc[0], sh[0]); y[1] = fmaf(v.y, sc[1], sh[1]);
    y[2] = fmaf(v.z, sc[2], sh[2]); y[3] = fmaf(v.w, sc[3], sh[3]);
    float ss = y[0]*y[0] + y[1]*y[1] + y[2]*y[2] + y[3]*y[3];
    #pragma unroll
    for (int o = 16; o > 0; o >>= 1) ss += __shfl_xor_sync(0xffffffffu, ss, o);
    float inv = rsqrtf(ss);
    __half2 p0 = __floats2half2_rn(y[0]*inv, y[1]*inv);
    __half2 p1 = __floats2half2_rn(y[2]*inv, y[3]*inv);
    uint2 pk = make_uint2(*(uint32_t*)&p0, *(uint32_t*)&p1);
    *(uint2*)&dst[(size_t)r*FD + l*4] = pk;
}

// ---------------- FUSED persistent gemm + select ------------------------------------------
// 444 CTAs x 256 thr, 3/SM. Queue: [0, 64*nty) gemm tiles (x-fastest), then g_cnt select rows.
// gemm: R12 config — CTA tile 128x128, 8 warps 64x32, fp16 acc, smem A 32KB | B 32KB.
// select: 256 threads, 32 elems/thread, two passes over L2-resident row.
#define SM_GEMM 65536

__global__ __launch_bounds__(256, 3) void k_fused() {
    extern __shared__ char smc[];
    __shared__ int s_item;
    uint32_t sb = smem_to_u32(smc);
    int tid = threadIdx.x, lane = tid & 31, wid = tid >> 5;
    int nty = (g_cnt + 127) >> 7;
    int ngemm = nty * 64;
    int total = ngemm + g_cnt;

    // gemm lane geometry (loop-invariant)
    int wm = wid >> 2, wn = wid & 3;
    int a_sub   = lane >> 3;
    int a_rowin = (lane & 7) + ((a_sub & 1) << 3);
    int a_cb    = a_sub >> 1;
    int b_rowin = lane & 7;
    int b_cb    = (lane >> 3) & 1;
    int gq = lane >> 2, tq = lane & 3;

    uint32_t aBase[4], bBase[4];
    int aM7[4], bM7[4];
    #pragma unroll
    for (int i = 0; i < 4; i++) {
        int row = wm * 64 + i * 16 + a_rowin;
        aBase[i] = sb + row * 256;
        aM7[i] = row & 7;
        int rn = wn * 32 + i * 8 + b_rowin;
        bBase[i] = sb + 32768 + rn * 256;
        bM7[i] = rn & 7;
    }

    // select smem views (reuse gemm buffers)
    int*   hist = (int*)smc;            // 4096 ints
    int*   wtot = (int*)(smc + 16384);  // 8
    int*   wsuf = (int*)(smc + 16416);  // 8
    int*   misc = (int*)(smc + 16448);  // 4
    int*   h16  = (int*)(smc + 16464);  // 16
    float* wz   = (float*)(smc + 16528);// 8

    while (true) {
        if (tid == 0) s_item = atomicAdd(&g_tile, 1);
        __syncthreads();
        int item = s_item;
        if (item >= total) break;

        if (item < ngemm) {
            // ---------------- gemm tile ----------------
            int xb = item & 63, yb = item >> 6;
            const int* mrow = &g_matched[yb * 128];

            #pragma unroll
            for (int it = 0; it < 8; it++) {
                int idx = tid + it * 256;
                int row = idx >> 4, ch = idx & 15;
                uint32_t swz = (uint32_t)((ch & 8) | ((ch ^ row) & 7));
                uint32_t off = (uint32_t)row * 256 + (swz << 4);
                int ar = __ldg(&mrow[row]);
                cp16(sb + off,         (const char*)(g_Ah + (size_t)ar * FD) + ch * 16);
                cp16(sb + 32768 + off, (const char*)(g_Bh + (size_t)(xb * 128 + row) * FD) + ch * 16);
            }
            cp_commit_wait();
            __syncthreads();

            uint32_t acc2[4][4][2];
            #pragma unroll
            for (int i = 0; i < 4; i++)
                #pragma unroll
                for (int j = 0; j < 4; j++) { acc2[i][j][0] = 0u; acc2[i][j][1] = 0u; }

            #pragma unroll
            for (int ks = 0; ks < 8; ks++) {
                int k2 = ks * 2;
                uint32_t aF[4][4], bF[4][2];
                #pragma unroll
                for (int i = 0; i < 4; i++) {
                    int c = k2 + a_cb;
                    uint32_t swz = (uint32_t)((c & 8) | ((c ^ aM7[i]) & 7));
                    ldm_x4(aF[i], aBase[i] + (swz << 4));
                }
                #pragma unroll
                for (int j = 0; j < 4; j++) {
                    int c = k2 + b_cb;
                    uint32_t swz = (uint32_t)((c & 8) | ((c ^ bM7[j]) & 7));
                    ldm_x2(bF[j], bBase[j] + (swz << 4));
                }
                #pragma unroll
                for (int i = 0; i < 4; i++)
                    #pragma unroll
                    for (int j = 0; j < 4; j++)
                        mma_f16acc(acc2[i][j], aF[i], bF[j]);
            }

            size_t rowbase = (size_t)yb * 128 + wm * 64 + gq;
            int colbase = xb * 128 + wn * 32 + tq * 2;
            #pragma unroll
            for (int i = 0; i < 4; i++) {
                #pragma unroll
                for (int j = 0; j < 4; j++) {
                    size_t r0 = (rowbase + i*16) * NT + colbase + j*8;
                    __half2 h0 = *(__half2*)&acc2[i][j][0];
                    __half2 h1 = *(__half2*)&acc2[i][j][1];
                    int q0 = __float2int_rn(__low2float(h0)  * QSCALE);
                    int q1 = __float2int_rn(__high2float(h0) * QSCALE);
                    int q2 = __float2int_rn(__low2float(h1)  * QSCALE);
                    int q3 = __float2int_rn(__high2float(h1) * QSCALE);
                    *(uint32_t*)&g_simsq[r0]                 = (q0 & 0xFFFF) | (q1 << 16);
                    *(uint32_t*)&g_simsq[r0 + (size_t)8*NT]  = (q2 & 0xFFFF) | (q3 << 16);
                }
            }
            __threadfence();
            __syncthreads();
            if (tid == 0) atomicAdd(&g_ready[yb], 1);   // release: tile complete
        } else {
            // ---------------- select row ----------------
            int r = item - ngemm;
            int yb = r >> 7;
            if (tid == 0) {
                while (atomicAdd(&g_ready[yb], 0) < 64) __nanosleep(128);
            }
            __syncthreads();
            __threadfence();

            for (int i = tid; i < 4096; i += 256) hist[i] = 0;
            if (tid < 16) h16[tid] = 0;
            __syncthreads();

            const uint4* g4 = (const uint4*)(g_simsq + (size_t)r * NT);
            #pragma unroll
            for (int u = 0; u < 4; u++) {
                uint4 v = g4[tid + u * 256];
                uint32_t ws[4] = {v.x, v.y, v.z, v.w};
                #pragma unroll
                for (int p = 0; p < 4; p++) {
                    int q0 = (int)(short)(ws[p] & 0xFFFF);
                    int q1 = (int)(short)(ws[p] >> 16);
                    atomicAdd(&hist[(q0 + 32768) >> 4], 1);
                    atomicAdd(&hist[(q1 + 32768) >> 4], 1);
                }
            }
            __syncthreads();

            // suffix scan: 16 bins per thread, 8 warps
            int cs = 0;
            #pragma unroll
            for (int i = 0; i < 16; i++) cs += hist[tid*16 + i];
            int x = cs;
            #pragma unroll
            for (int off = 1; off < 32; off <<= 1) {
                int yv = __shfl_down_sync(0xffffffffu, x, off);
                if (lane + off < 32) x += yv;
            }
            if (lane == 0) wtot[wid] = x;
            __syncthreads();
            if (tid < 8) {
                int s = 0;
                for (int ww = tid + 1; ww < 8; ww++) s += wtot[ww];
                wsuf[tid] = s;
            }
            __syncthreads();
            int incl = x + wsuf[wid];
            int excl = incl - cs;
            if (incl >= KSEL && excl < KSEL) {
                int cum = excl;
                for (int b = tid*16 + 15; b >= tid*16; b--) {
                    cum += hist[b];
                    if (cum >= KSEL) { misc[0] = b; misc[1] = KSEL - (cum - hist[b]); break; }
                }
            }
            __syncthreads();
            int B = misc[0], j = misc[1];
            int C = (B << 4) - 32768;

            // pass 2: reload row (L2-hot), sum exp over bins > B, tally boundary slots
            float z = 0.f;
            #pragma unroll
            for (int u = 0; u < 4; u++) {
                uint4 v = g4[tid + u * 256];
                uint32_t ws[4] = {v.x, v.y, v.z, v.w};
                #pragma unroll
                for (int p = 0; p < 4; p++) {
                    int q0 = (int)(short)(ws[p] & 0xFFFF);
                    int q1 = (int)(short)(ws[p] >> 16);
                    int b0 = (q0 + 32768) >> 4;
                    int b1 = (q1 + 32768) >> 4;
                    if (b0 > B) z += fexp((float)(q0 - C) * INV2048);
                    else if (b0 == B) atomicAdd(&h16[(q0 + 32768) & 15], 1);
                    if (b1 > B) z += fexp((float)(q1 - C) * INV2048);
                    else if (b1 == B) atomicAdd(&h16[(q1 + 32768) & 15], 1);
                }
            }
            #pragma unroll
            for (int o = 16; o > 0; o >>= 1) z += __shfl_xor_sync(0xffffffffu, z, o);
            if (lane == 0) wz[wid] = z;
            __syncthreads();

            if (tid == 0) {
                float Z = 0.f;
                #pragma unroll
                for (int i = 0; i < 8; i++) Z += wz[i];
                int need = j;
                for (int s = 15; s >= 0 && need > 0; s--) {
                    int c = h16[s];
                    if (c == 0) continue;
                    int take = min(c, need);
                    int q = B*16 + s - 32768;
                    Z += (float)take * fexp((float)(q - C) * INV2048);
                    need -= take;
                }
                int srow = g_matched[r];
                int qpos = (int)((const short*)g_simsq)[(size_t)r * NT + g_tidx[srow]];
                Z += fexp((float)(qpos - C) * INV2048);
                float pp = logf(Z) + (float)(C - qpos) * INV2048;
                atomicAdd(&g_accum, pp);
            }
        }
        __syncthreads();   // smem reuse + s_item overwrite guard
    }
}

// ---------------- finalize + keymap restore -----------------------------------------------
__global__ void k_fin(const int* __restrict__ tc, float* out) {
    int i = blockIdx.x * 256 + threadIdx.x;
    int4 c = ((const int4*)tc)[i];
    int key = ((c.x * 64 + c.y) * 128 + c.z) * 128 + c.w;
    g_keymap[key] = 0;
    if (i == 0) {
        int cnt = g_cnt;
        float d = (cnt > 0) ? (float)cnt : 1.0f;
        out[0] = g_accum / d;
    }
}

// ---------------- launch ------------------------------------------------------------------
extern "C" void kernel_launch(void* const* d_in, const int* in_sizes, int n_in,
                              void* d_out, int out_size) {
    const float* tf = (const float*)d_in[0];
    const float* sf = (const float*)d_in[1];
    const float* t_w1 = (const float*)d_in[2];
    const float* t_b1 = (const float*)d_in[3];
    const float* t_w2 = (const float*)d_in[4];
    const float* t_b2 = (const float*)d_in[5];
    const float* t_g  = (const float*)d_in[6];
    const float* t_be = (const float*)d_in[7];
    const float* s_w1 = (const float*)d_in[8];
    const float* s_b1 = (const float*)d_in[9];
    const float* s_w2 = (const float*)d_in[10];
    const float* s_b2 = (const float*)d_in[11];
    const float* s_g  = (const float*)d_in[12];
    const float* s_be = (const float*)d_in[13];
    const int* tco = (const int*)d_in[14];
    const int* sco = (const int*)d_in[15];

    cudaFuncSetAttribute(k_projmma, cudaFuncAttributeMaxDynamicSharedMemorySize, SM_PROJ);
    cudaFuncSetAttribute(k_fused,   cudaFuncAttributeMaxDynamicSharedMemorySize, SM_GEMM);

    k_prep<<<32, 256>>>(tco, t_w1, t_w2, s_w1, s_w2);           // 0
    k_projmma<<<dim3(64,1,2), 256, SM_PROJ>>>(tf, sf,           // 1 (+ distributed match)
        t_b1, t_b2, s_b1, s_b2, sco);
    k_normsplit<<<dim3(1024,1,2), 256>>>(t_g, t_be, s_g, s_be); // 2
    k_fused<<<444, 256, SM_GEMM>>>();                           // 3  <- ncu captures this
    k_fin<<<32, 256>>>(tco, (float*)d_out);                     // 4
}

// round 15
// speedup vs baseline: 1.1143x; 1.1143x over previous
#include <cuda_runtime.h>
#include <cuda_bf16.h>
#include <cuda_fp16.h>
#include <math.h>
#include <stdint.h>

#define NT 8192
#define NS 8192
#define FD 128
#define KSEL 2457
#define BN_EPS 1e-5f
#define INV_TAU (1.0f/0.07f)
#define QSCALE (INV_TAU * 2048.0f)
#define INV2048 4.8828125e-4f
#define KEYSPACE (2*64*128*128)

// ---------------- scratch (device globals) --------------------------------------------
__device__ __align__(16) float g_h2[2][NS*FD];
__device__ __align__(16) unsigned short g_simsq[(size_t)NS*NT];  // 128MB
__device__ __align__(16) __half g_Ah[NS*FD];   // student projections, fp16
__device__ __align__(16) __half g_Bh[NT*FD];   // teacher projections, fp16
__device__ __align__(16) uint4 g_wq[2][2][2][2048];  // [net][layer][hi/lo] swizzled bf16 chunks
__device__ int   g_keymap[KEYSPACE];   // 0 = empty; restored by k_fin each launch
__device__ int   g_matched[NS];
__device__ int   g_tidx[NS];
__device__ int   g_cnt;
__device__ float g_accum;
__device__ float g_bn_sum[2][FD];
__device__ float g_bn_sq[2][FD];

// ---------------- helpers ---------------------------------------------------------------
__device__ __forceinline__ uint32_t smem_to_u32(const void* p) {
    uint32_t a;
    asm("{ .reg .u64 t; cvta.to.shared.u64 t, %1; cvt.u32.u64 %0, t; }" : "=r"(a) : "l"(p));
    return a;
}
__device__ __forceinline__ void cp16(uint32_t s, const void* g) {
    asm volatile("cp.async.cg.shared.global [%0], [%1], 16;" :: "r"(s), "l"(g));
}
__device__ __forceinline__ void cp_commit_wait() {
    asm volatile("cp.async.commit_group;");
    asm volatile("cp.async.wait_group 0;");
}
__device__ __forceinline__ void ldm_x4(uint32_t* r, uint32_t addr) {
    asm volatile("ldmatrix.sync.aligned.m8n8.x4.shared.b16 {%0,%1,%2,%3}, [%4];"
        : "=r"(r[0]), "=r"(r[1]), "=r"(r[2]), "=r"(r[3]) : "r"(addr));
}
__device__ __forceinline__ void ldm_x2(uint32_t* r, uint32_t addr) {
    asm volatile("ldmatrix.sync.aligned.m8n8.x2.shared.b16 {%0,%1}, [%2];"
        : "=r"(r[0]), "=r"(r[1]) : "r"(addr));
}
__device__ __forceinline__ void mma_bf16(float* c, const uint32_t* a, const uint32_t* b) {
    asm volatile("mma.sync.aligned.m16n8k16.row.col.f32.bf16.bf16.f32 "
        "{%0,%1,%2,%3}, {%4,%5,%6,%7}, {%8,%9}, {%0,%1,%2,%3};"
        : "+f"(c[0]), "+f"(c[1]), "+f"(c[2]), "+f"(c[3])
        : "r"(a[0]), "r"(a[1]), "r"(a[2]), "r"(a[3]), "r"(b[0]), "r"(b[1]));
}
// fp16-accumulator MMA: D(half2 x2) = A*B + C
__device__ __forceinline__ void mma_f16acc(uint32_t* c, const uint32_t* a, const uint32_t* b) {
    asm volatile("mma.sync.aligned.m16n8k16.row.col.f16.f16.f16.f16 "
        "{%0,%1}, {%2,%3,%4,%5}, {%6,%7}, {%0,%1};"
        : "+r"(c[0]), "+r"(c[1])
        : "r"(a[0]), "r"(a[1]), "r"(a[2]), "r"(a[3]), "r"(b[0]), "r"(b[1]));
}
__device__ __forceinline__ float fexp(float x) {
    float y = x * 1.44269504088896340736f;
    float n = rintf(y);
    float t = (y - n) * 0.69314718055994530942f;
    float p = 1.0f/720.0f;
    p = fmaf(p, t, 1.0f/120.0f);
    p = fmaf(p, t, 1.0f/24.0f);
    p = fmaf(p, t, 1.0f/6.0f);
    p = fmaf(p, t, 0.5f);
    p = fmaf(p, t, 1.0f);
    p = fmaf(p, t, 1.0f);
    int ni = (int)n;
    return p * __int_as_float((ni + 127) << 23);
}
__device__ __forceinline__ uint32_t pack_hi(float a, float b) {
    __nv_bfloat16 h0 = __float2bfloat16(a), h1 = __float2bfloat16(b);
    return (uint32_t)__bfloat16_as_ushort(h0) | ((uint32_t)__bfloat16_as_ushort(h1) << 16);
}
__device__ __forceinline__ uint32_t pack_lo(float a, float b) {
    __nv_bfloat16 h0 = __float2bfloat16(a), h1 = __float2bfloat16(b);
    float r0 = a - __bfloat162float(h0), r1 = b - __bfloat162float(h1);
    __nv_bfloat16 l0 = __float2bfloat16(r0), l1 = __float2bfloat16(r1);
    return (uint32_t)__bfloat16_as_ushort(l0) | ((uint32_t)__bfloat16_as_ushort(l1) << 16);
}

// ---------------- prep: scatter keys + clears + weight transpose/split -------------------
__global__ void k_prep(const int* __restrict__ tc,
                       const float* __restrict__ tw1, const float* __restrict__ tw2,
                       const float* __restrict__ sw1, const float* __restrict__ sw2) {
    int i = blockIdx.x * 256 + threadIdx.x;
    int4 c = ((const int4*)tc)[i];
    int key = ((c.x * 64 + c.y) * 128 + c.z) * 128 + c.w;
    g_keymap[key] = i + 1;
    g_matched[i] = 0;
    if (i < 2*FD) {
        ((float*)g_bn_sum)[i] = 0.f;
        ((float*)g_bn_sq)[i]  = 0.f;
    }
    if (i == 0) { g_cnt = 0; g_accum = 0.f; }

    // weight transpose: all 8192 threads, one (net,layer,n,kg,half) each
    {
        int half = i & 1, kg = (i >> 1) & 7, n = (i >> 4) & 127;
        int layer = (i >> 11) & 1, net = i >> 12;
        const float* w = net ? (layer ? sw2 : sw1) : (layer ? tw2 : tw1);
        int kb = kg * 16 + half * 8;
        uint32_t hw[4], lw[4];
        #pragma unroll
        for (int q = 0; q < 4; q++) {
            float v0 = w[(kb + q*2    ) * 128 + n];
            float v1 = w[(kb + q*2 + 1) * 128 + n];
            hw[q] = pack_hi(v0, v1);
            lw[q] = pack_lo(v0, v1);
        }
        int ch = kg * 2 + half;
        int idx = n * 16 + (ch ^ (n & 7));
        g_wq[net][layer][0][idx] = make_uint4(hw[0], hw[1], hw[2], hw[3]);
        g_wq[net][layer][1][idx] = make_uint4(lw[0], lw[1], lw[2], lw[3]);
    }
}

// ---------------- fused 2-layer projection via HMMA hi/lo (+ distributed match) ----------
#define PJ_XH 0
#define PJ_XL 32768
#define PJ_W1H 65536
#define PJ_W1L 98304
#define PJ_W2H 131072
#define PJ_W2L 163840
#define PJ_BIAS 196608
#define PJ_CS 197632
#define PJ_CQ 198144
#define SM_PROJ 198656

__global__ __launch_bounds__(256) void k_projmma(
    const float* __restrict__ tf, const float* __restrict__ sf,
    const float* __restrict__ tb1, const float* __restrict__ tb2,
    const float* __restrict__ sb1, const float* __restrict__ sb2,
    const int* __restrict__ sco)
{
    extern __shared__ char smc[];
    uint32_t sb = smem_to_u32(smc);
    float* smf = (float*)smc;
    int net = blockIdx.z;
    const float* x  = net ? sf : tf;
    const float* b1 = net ? sb1 : tb1;
    const float* b2 = net ? sb2 : tb2;
    int tid = threadIdx.x;
    int r0 = blockIdx.x * 128;

    // distributed coordinate matching: 64 student rows per CTA (128 CTAs total)
    if (tid < 64) {
        int j0 = (net * 64 + blockIdx.x) * 64 + tid;
        int4 c = ((const int4*)sco)[j0];
        int key = ((c.x * 64 + c.y) * 128 + c.z) * 128 + c.w;
        int t = g_keymap[key] - 1;
        g_tidx[j0] = (t < 0) ? 0 : t;
        unsigned m = __ballot_sync(0xffffffffu, t >= 0);
        int base = 0;
        if ((tid & 31) == 0) base = atomicAdd(&g_cnt, __popc(m));
        base = __shfl_sync(0xffffffffu, base, 0);
        if (t >= 0) {
            int rank = __popc(m & ((1u << (tid & 31)) - 1u));
            g_matched[base + rank] = j0;
        }
    }

    // load X fp32 -> hi/lo bf16 swizzled smem
    #pragma unroll
    for (int it = 0; it < 8; it++) {
        int cidx = tid + it * 256;
        int row = cidx >> 4, ch = cidx & 15;
        const float4* src = (const float4*)(x + (size_t)(r0 + row) * FD + ch * 8);
        float4 f0 = src[0], f1 = src[1];
        uint4 hv, lv;
        hv.x = pack_hi(f0.x, f0.y); lv.x = pack_lo(f0.x, f0.y);
        hv.y = pack_hi(f0.z, f0.w); lv.y = pack_lo(f0.z, f0.w);
        hv.z = pack_hi(f1.x, f1.y); lv.z = pack_lo(f1.x, f1.y);
        hv.w = pack_hi(f1.z, f1.w); lv.w = pack_lo(f1.z, f1.w);
        uint32_t off = (uint32_t)row * 256 + (uint32_t)((ch ^ (row & 7)) << 4);
        *(uint4*)(smc + PJ_XH + off) = hv;
        *(uint4*)(smc + PJ_XL + off) = lv;
    }
    #pragma unroll
    for (int it = 0; it < 8; it++) {
        int cidx = tid + it * 256;
        ((uint4*)(smc + PJ_W1H))[cidx] = g_wq[net][0][0][cidx];
        ((uint4*)(smc + PJ_W1L))[cidx] = g_wq[net][0][1][cidx];
        ((uint4*)(smc + PJ_W2H))[cidx] = g_wq[net][1][0][cidx];
        ((uint4*)(smc + PJ_W2L))[cidx] = g_wq[net][1][1][cidx];
    }
    if (tid < 128) {
        smf[PJ_BIAS/4 + tid]       = b1[tid];
        smf[PJ_BIAS/4 + 128 + tid] = b2[tid];
        smf[PJ_CS/4 + tid] = 0.f;
        smf[PJ_CQ/4 + tid] = 0.f;
    }
    __syncthreads();

    int lane = tid & 31, wid = tid >> 5;
    int wm = wid >> 2, wn = wid & 3;
    int a_sub   = lane >> 3;
    int a_rowin = (lane & 7) + ((a_sub & 1) << 3);
    int a_cb    = a_sub >> 1;
    int b_rowin = lane & 7;
    int b_cb    = (lane >> 3) & 1;
    int g = lane >> 2, t = lane & 3;

    uint32_t aBase[4], bBase[4];
    int aM7[4], bM7[4];
    #pragma unroll
    for (int i = 0; i < 4; i++) {
        int row = wm * 64 + i * 16 + a_rowin;
        aBase[i] = sb + PJ_XH + row * 256;
        aM7[i] = row & 7;
        int rn = wn * 32 + i * 8 + b_rowin;
        bBase[i] = sb + rn * 256;
        bM7[i] = rn & 7;
    }

    float acc[4][4][4];

    // ---- layer 1 ----
    #pragma unroll
    for (int i = 0; i < 4; i++)
        #pragma unroll
        for (int j = 0; j < 4; j++)
            #pragma unroll
            for (int q = 0; q < 4; q++) acc[i][j][q] = 0.f;
    #pragma unroll
    for (int ks = 0; ks < 8; ks++) {
        int k2 = ks * 2;
        uint32_t aH[4][4], aL[4][4], bH[4][2], bL[4][2];
        #pragma unroll
        for (int i = 0; i < 4; i++) {
            uint32_t ad = aBase[i] + (((k2 + a_cb) ^ aM7[i]) << 4);
            ldm_x4(aH[i], ad);
            ldm_x4(aL[i], ad + 32768);
        }
        #pragma unroll
        for (int j = 0; j < 4; j++) {
            uint32_t bd = bBase[j] + PJ_W1H + (((k2 + b_cb) ^ bM7[j]) << 4);
            ldm_x2(bH[j], bd);
            ldm_x2(bL[j], bd + 32768);
        }
        #pragma unroll
        for (int i = 0; i < 4; i++)
            #pragma unroll
            for (int j = 0; j < 4; j++) {
                mma_bf16(acc[i][j], aH[i], bH[j]);
                mma_bf16(acc[i][j], aH[i], bL[j]);
                mma_bf16(acc[i][j], aL[i], bH[j]);
            }
    }
    __syncthreads();

    // bias + relu + re-split into XH/XL (now H1)
    #pragma unroll
    for (int i = 0; i < 4; i++) {
        #pragma unroll
        for (int j = 0; j < 4; j++) {
            int col0 = wn * 32 + j * 8 + t * 2;
            float bb0 = smf[PJ_BIAS/4 + col0], bb1 = smf[PJ_BIAS/4 + col0 + 1];
            float v0 = fmaxf(acc[i][j][0] + bb0, 0.f);
            float v1 = fmaxf(acc[i][j][1] + bb1, 0.f);
            float v2 = fmaxf(acc[i][j][2] + bb0, 0.f);
            float v3 = fmaxf(acc[i][j][3] + bb1, 0.f);
            int rl = wm * 64 + i * 16 + g, rh = rl + 8;
            uint32_t offl = rl * 256 + (((col0 >> 3) ^ (rl & 7)) << 4) + (col0 & 7) * 2;
            uint32_t offh = rh * 256 + (((col0 >> 3) ^ (rh & 7)) << 4) + (col0 & 7) * 2;
            *(uint32_t*)(smc + PJ_XH + offl) = pack_hi(v0, v1);
            *(uint32_t*)(smc + PJ_XL + offl) = pack_lo(v0, v1);
            *(uint32_t*)(smc + PJ_XH + offh) = pack_hi(v2, v3);
            *(uint32_t*)(smc + PJ_XL + offh) = pack_lo(v2, v3);
        }
    }
    __syncthreads();

    // ---- layer 2 ----
    #pragma unroll
    for (int i = 0; i < 4; i++)
        #pragma unroll
        for (int j = 0; j < 4; j++)
            #pragma unroll
            for (int q = 0; q < 4; q++) acc[i][j][q] = 0.f;
    #pragma unroll
    for (int ks = 0; ks < 8; ks++) {
        int k2 = ks * 2;
        uint32_t aH[4][4], aL[4][4], bH[4][2], bL[4][2];
        #pragma unroll
        for (int i = 0; i < 4; i++) {
            uint32_t ad = aBase[i] + (((k2 + a_cb) ^ aM7[i]) << 4);
            ldm_x4(aH[i], ad);
            ldm_x4(aL[i], ad + 32768);
        }
        #pragma unroll
        for (int j = 0; j < 4; j++) {
            uint32_t bd = bBase[j] + PJ_W2H + (((k2 + b_cb) ^ bM7[j]) << 4);
            ldm_x2(bH[j], bd);
            ldm_x2(bL[j], bd + 32768);
        }
        #pragma unroll
        for (int i = 0; i < 4; i++)
            #pragma unroll
            for (int j = 0; j < 4; j++) {
                mma_bf16(acc[i][j], aH[i], bH[j]);
                mma_bf16(acc[i][j], aH[i], bL[j]);
                mma_bf16(acc[i][j], aL[i], bH[j]);
            }
    }

    float* out = g_h2[net];
    #pragma unroll
    for (int j = 0; j < 4; j++) {
        int col0 = wn * 32 + j * 8 + t * 2;
        float bb0 = smf[PJ_BIAS/4 + 128 + col0], bb1 = smf[PJ_BIAS/4 + 128 + col0 + 1];
        float s0 = 0.f, q0 = 0.f, s1 = 0.f, q1 = 0.f;
        #pragma unroll
        for (int i = 0; i < 4; i++) {
            float v0 = acc[i][j][0] + bb0;
            float v1 = acc[i][j][1] + bb1;
            float v2 = acc[i][j][2] + bb0;
            float v3 = acc[i][j][3] + bb1;
            int rl = wm * 64 + i * 16 + g, rh = rl + 8;
            *(float2*)&out[(size_t)(r0 + rl) * FD + col0] = make_float2(v0, v1);
            *(float2*)&out[(size_t)(r0 + rh) * FD + col0] = make_float2(v2, v3);
            s0 += v0 + v2; q0 += v0*v0 + v2*v2;
            s1 += v1 + v3; q1 += v1*v1 + v3*v3;
        }
        atomicAdd(&smf[PJ_CS/4 + col0], s0);
        atomicAdd(&smf[PJ_CQ/4 + col0], q0);
        atomicAdd(&smf[PJ_CS/4 + col0 + 1], s1);
        atomicAdd(&smf[PJ_CQ/4 + col0 + 1], q1);
    }
    __syncthreads();
    if (tid < 128) {
        atomicAdd(&g_bn_sum[net][tid], smf[PJ_CS/4 + tid]);
        atomicAdd(&g_bn_sq[net][tid],  smf[PJ_CQ/4 + tid]);
    }
}

// ---------------- fused BNfinal + BN apply + L2 normalize + fp16 convert ------------------
__global__ void k_normsplit(const float* __restrict__ tg, const float* __restrict__ tbe,
                            const float* __restrict__ sg, const float* __restrict__ sbe) {
    int net = blockIdx.z;
    const float* h = g_h2[net];
    const float* gam = net ? sg : tg;
    const float* bet = net ? sbe : tbe;
    __half* dst = net ? g_Ah : g_Bh;
    int w = threadIdx.x >> 5, l = threadIdx.x & 31;
    int r = blockIdx.x * 8 + w;

    float4 su = *(const float4*)&g_bn_sum[net][l*4];
    float4 sq = *(const float4*)&g_bn_sq[net][l*4];
    float4 gm = *(const float4*)&gam[l*4];
    float4 bt = *(const float4*)&bet[l*4];
    float sc[4], sh[4];
    {
        float mu, var;
        mu = su.x*(1.f/8192.f); var = sq.x*(1.f/8192.f) - mu*mu;
        sc[0] = rsqrtf(var + BN_EPS) * gm.x; sh[0] = bt.x - mu * sc[0];
        mu = su.y*(1.f/8192.f); var = sq.y*(1.f/8192.f) - mu*mu;
        sc[1] = rsqrtf(var + BN_EPS) * gm.y; sh[1] = bt.y - mu * sc[1];
        mu = su.z*(1.f/8192.f); var = sq.z*(1.f/8192.f) - mu*mu;
        sc[2] = rsqrtf(var + BN_EPS) * gm.z; sh[2] = bt.z - mu * sc[2];
        mu = su.w*(1.f/8192.f); var = sq.w*(1.f/8192.f) - mu*mu;
        sc[3] = rsqrtf(var + BN_EPS) * gm.w; sh[3] = bt.w - mu * sc[3];
    }
    float4 v = *(const float4*)&h[(size_t)r*FD + l*4];
    float y[4];
    y[0] = fmaf(v.x, sc[0], sh[0]); y[1] = fmaf(v.y, sc[1], sh[1]);
    y[2] = fmaf(v.z, sc[2], sh[2]); y[3] = fmaf(v.w, sc[3], sh[3]);
    float ss = y[0]*y[0] + y[1]*y[1] + y[2]*y[2] + y[3]*y[3];
    #pragma unroll
    for (int o = 16; o > 0; o >>= 1) ss += __shfl_xor_sync(0xffffffffu, ss, o);
    float inv = rsqrtf(ss);
    __half2 p0 = __floats2half2_rn(y[0]*inv, y[1]*inv);
    __half2 p1 = __floats2half2_rn(y[2]*inv, y[3]*inv);
    uint2 pk = make_uint2(*(uint32_t*)&p0, *(uint32_t*)&p1);
    *(uint2*)&dst[(size_t)r*FD + l*4] = pk;
}

// ---------------- fp16 HMMA GEMM, fp16 accumulators, 3 CTA/SM (R12 config) ----------------
// smem: A fp16 [128 x 128] at 0 (32KB), B at 32768 (32KB). row = 256B = 16 chunks.
// swizzle: swz(ch,row) = (ch & 8) | ((ch ^ row) & 7)
#define SM_GEMM 65536

__global__ __launch_bounds__(256, 3) void k_gemm() {
    if ((int)(blockIdx.y * 128) >= g_cnt) return;
    extern __shared__ char smc[];
    uint32_t sb = smem_to_u32(smc);
    int tid = threadIdx.x, lane = tid & 31, wid = tid >> 5;
    int wm = wid >> 2, wn = wid & 3;        // warp tile 64x32
    const int* mrow = &g_matched[blockIdx.y * 128];

    // cooperative cp.async fill: 2048 A chunks + 2048 B chunks (16B each)
    #pragma unroll
    for (int it = 0; it < 8; it++) {
        int idx = tid + it * 256;
        int row = idx >> 4, ch = idx & 15;
        uint32_t swz = (uint32_t)((ch & 8) | ((ch ^ row) & 7));
        uint32_t off = (uint32_t)row * 256 + (swz << 4);
        int ar = __ldg(&mrow[row]);
        cp16(sb + off,         (const char*)(g_Ah + (size_t)ar * FD) + ch * 16);
        cp16(sb + 32768 + off, (const char*)(g_Bh + (size_t)(blockIdx.x * 128 + row) * FD) + ch * 16);
    }
    cp_commit_wait();
    __syncthreads();

    int a_sub   = lane >> 3;
    int a_rowin = (lane & 7) + ((a_sub & 1) << 3);
    int a_cb    = a_sub >> 1;
    int b_rowin = lane & 7;
    int b_cb    = (lane >> 3) & 1;

    uint32_t aBase[4], bBase[4];
    int aM7[4], bM7[4];
    #pragma unroll
    for (int i = 0; i < 4; i++) {
        int row = wm * 64 + i * 16 + a_rowin;
        aBase[i] = sb + row * 256;
        aM7[i] = row & 7;
        int rn = wn * 32 + i * 8 + b_rowin;
        bBase[i] = sb + 32768 + rn * 256;
        bM7[i] = rn & 7;
    }

    uint32_t acc2[4][4][2];
    #pragma unroll
    for (int i = 0; i < 4; i++)
        #pragma unroll
        for (int j = 0; j < 4; j++) { acc2[i][j][0] = 0u; acc2[i][j][1] = 0u; }

    #pragma unroll
    for (int ks = 0; ks < 8; ks++) {
        int k2 = ks * 2;
        uint32_t aF[4][4], bF[4][2];
        #pragma unroll
        for (int i = 0; i < 4; i++) {
            int c = k2 + a_cb;
            uint32_t swz = (uint32_t)((c & 8) | ((c ^ aM7[i]) & 7));
            ldm_x4(aF[i], aBase[i] + (swz << 4));
        }
        #pragma unroll
        for (int j = 0; j < 4; j++) {
            int c = k2 + b_cb;
            uint32_t swz = (uint32_t)((c & 8) | ((c ^ bM7[j]) & 7));
            ldm_x2(bF[j], bBase[j] + (swz << 4));
        }
        #pragma unroll
        for (int i = 0; i < 4; i++)
            #pragma unroll
            for (int j = 0; j < 4; j++)
                mma_f16acc(acc2[i][j], aF[i], bF[j]);
    }

    // epilogue: half2 -> int16 quant, pack pairs, store
    int g = lane >> 2, t = lane & 3;
    size_t rowbase = (size_t)blockIdx.y * 128 + wm * 64 + g;
    int colbase = blockIdx.x * 128 + wn * 32 + t * 2;
    #pragma unroll
    for (int i = 0; i < 4; i++) {
        #pragma unroll
        for (int j = 0; j < 4; j++) {
            size_t r0 = (rowbase + i*16) * NT + colbase + j*8;
            __half2 h0 = *(__half2*)&acc2[i][j][0];
            __half2 h1 = *(__half2*)&acc2[i][j][1];
            int q0 = __float2int_rn(__low2float(h0)  * QSCALE);
            int q1 = __float2int_rn(__high2float(h0) * QSCALE);
            int q2 = __float2int_rn(__low2float(h1)  * QSCALE);
            int q3 = __float2int_rn(__high2float(h1) * QSCALE);
            *(uint32_t*)&g_simsq[r0]                 = (q0 & 0xFFFF) | (q1 << 16);
            *(uint32_t*)&g_simsq[r0 + (size_t)8*NT]  = (q2 & 0xFFFF) | (q3 << 16);
        }
    }
}

// ---------------- exact top-k + logsumexp: register row + dual hist, newest-first ---------
__global__ __launch_bounds__(512) void k_select() {
    int cnt = g_cnt;
    if (blockIdx.x >= cnt) return;
    int bid = cnt - 1 - blockIdx.x;      // newest-written rows first (L2-hot)
    __shared__ int hist[8192];           // two 4096-bin copies (warp-parity split)
    __shared__ int wtot[16];
    __shared__ int wsuf[16];
    __shared__ float wz[16];
    __shared__ int h16[16];
    __shared__ int misc[4];
    int tid = threadIdx.x, lane = tid & 31, wid = tid >> 5;

    #pragma unroll
    for (int i = 0; i < 4; i++) ((int4*)hist)[tid + i*512] = make_int4(0,0,0,0);
    if (tid < 16) h16[tid] = 0;
    __syncthreads();

    const uint4* g4 = (const uint4*)(g_simsq + (size_t)bid * NT);
    uint4 v0 = g4[tid], v1 = g4[tid + 512];
    uint32_t w[8] = {v0.x, v0.y, v0.z, v0.w, v1.x, v1.y, v1.z, v1.w};

    int* myh = hist + ((wid & 1) << 12);
    #pragma unroll
    for (int i = 0; i < 8; i++) {
        int q0 = (int)(short)(w[i] & 0xFFFF);
        int q1 = (int)(short)(w[i] >> 16);
        atomicAdd(&myh[(q0 + 32768) >> 4], 1);
        atomicAdd(&myh[(q1 + 32768) >> 4], 1);
    }
    __syncthreads();

    int cs = 0;
    #pragma unroll
    for (int i = 0; i < 8; i++) cs += hist[tid*8 + i] + hist[4096 + tid*8 + i];
    int x = cs;
    #pragma unroll
    for (int off = 1; off < 32; off <<= 1) {
        int yv = __shfl_down_sync(0xffffffffu, x, off);
        if (lane + off < 32) x += yv;
    }
    if (lane == 0) wtot[wid] = x;
    __syncthreads();
    if (tid < 16) {
        int s = 0;
        for (int ww = tid + 1; ww < 16; ww++) s += wtot[ww];
        wsuf[tid] = s;
    }
    __syncthreads();
    int incl = x + wsuf[wid];
    int excl = incl - cs;
    if (incl >= KSEL && excl < KSEL) {
        int cum = excl;
        for (int b = tid*8 + 7; b >= tid*8; b--) {
            cum += hist[b] + hist[4096 + b];
            if (cum >= KSEL) { misc[0] = b; misc[1] = KSEL - (cum - hist[b] - hist[4096 + b]); break; }
        }
    }
    __syncthreads();
    int B = misc[0], j = misc[1];
    int C = (B << 4) - 32768;

    float z = 0.f;
    #pragma unroll
    for (int i = 0; i < 8; i++) {
        int q0 = (int)(short)(w[i] & 0xFFFF);
        int q1 = (int)(short)(w[i] >> 16);
        int b0 = (q0 + 32768) >> 4;
        int b1 = (q1 + 32768) >> 4;
        if (b0 > B) z += fexp((float)(q0 - C) * INV2048);
        else if (b0 == B) atomicAdd(&h16[(q0 + 32768) & 15], 1);
        if (b1 > B) z += fexp((float)(q1 - C) * INV2048);
        else if (b1 == B) atomicAdd(&h16[(q1 + 32768) & 15], 1);
    }
    #pragma unroll
    for (int o = 16; o > 0; o >>= 1) z += __shfl_xor_sync(0xffffffffu, z, o);
    if (lane == 0) wz[wid] = z;
    __syncthreads();

    if (tid == 0) {
        float Z = 0.f;
        #pragma unroll
        for (int i = 0; i < 16; i++) Z += wz[i];
        int need = j;
        for (int s = 15; s >= 0 && need > 0; s--) {
            int c = h16[s];
            if (c == 0) continue;
            int take = min(c, need);
            int q = B*16 + s - 32768;
            Z += (float)take * fexp((float)(q - C) * INV2048);
            need -= take;
        }
        int srow = g_matched[bid];
        int qpos = (int)((const short*)g_simsq)[(size_t)bid * NT + g_tidx[srow]];
        Z += fexp((float)(qpos - C) * INV2048);
        float pp = logf(Z) + (float)(C - qpos) * INV2048;
        atomicAdd(&g_accum, pp);
    }
}

// ---------------- finalize + keymap restore -----------------------------------------------
__global__ void k_fin(const int* __restrict__ tc, float* out) {
    int i = blockIdx.x * 256 + threadIdx.x;
    int4 c = ((const int4*)tc)[i];
    int key = ((c.x * 64 + c.y) * 128 + c.z) * 128 + c.w;
    g_keymap[key] = 0;
    if (i == 0) {
        int cnt = g_cnt;
        float d = (cnt > 0) ? (float)cnt : 1.0f;
        out[0] = g_accum / d;
    }
}

// ---------------- launch ------------------------------------------------------------------
extern "C" void kernel_launch(void* const* d_in, const int* in_sizes, int n_in,
                              void* d_out, int out_size) {
    const float* tf = (const float*)d_in[0];
    const float* sf = (const float*)d_in[1];
    const float* t_w1 = (const float*)d_in[2];
    const float* t_b1 = (const float*)d_in[3];
    const float* t_w2 = (const float*)d_in[4];
    const float* t_b2 = (const float*)d_in[5];
    const float* t_g  = (const float*)d_in[6];
    const float* t_be = (const float*)d_in[7];
    const float* s_w1 = (const float*)d_in[8];
    const float* s_b1 = (const float*)d_in[9];
    const float* s_w2 = (const float*)d_in[10];
    const float* s_b2 = (const float*)d_in[11];
    const float* s_g  = (const float*)d_in[12];
    const float* s_be = (const float*)d_in[13];
    const int* tco = (const int*)d_in[14];
    const int* sco = (const int*)d_in[15];

    cudaFuncSetAttribute(k_projmma, cudaFuncAttributeMaxDynamicSharedMemorySize, SM_PROJ);
    cudaFuncSetAttribute(k_gemm,    cudaFuncAttributeMaxDynamicSharedMemorySize, SM_GEMM);

    k_prep<<<32, 256>>>(tco, t_w1, t_w2, s_w1, s_w2);           // 0
    k_projmma<<<dim3(64,1,2), 256, SM_PROJ>>>(tf, sf,           // 1 (+ distributed match)
        t_b1, t_b2, s_b1, s_b2, sco);
    k_normsplit<<<dim3(1024,1,2), 256>>>(t_g, t_be, s_g, s_be); // 2
    k_gemm<<<dim3(64, 64), 256, SM_GEMM>>>();                   // 3
    k_select<<<8192, 512>>>();                                  // 4
    k_fin<<<32, 256>>>(tco, (float*)d_out);                     // 5
}

// round 16
// speedup vs baseline: 1.2203x; 1.0951x over previous
#include <cuda_runtime.h>
#include <cuda_bf16.h>
#include <cuda_fp16.h>
#include <math.h>
#include <stdint.h>

#define NT 8192
#define NS 8192
#define FD 128
#define KSEL 2457
#define BN_EPS 1e-5f
#define INV_TAU (1.0f/0.07f)
#define QSCALE (INV_TAU * 2048.0f)
#define INV2048 4.8828125e-4f
#define KEYSPACE (2*64*128*128)

// ---------------- scratch (device globals) --------------------------------------------
__device__ __align__(16) float g_h2[2][NS*FD];
__device__ __align__(16) unsigned short g_simsq[(size_t)NS*NT];  // 128MB
__device__ __align__(16) __half g_Ah[NS*FD];   // student projections, fp16
__device__ __align__(16) __half g_Bh[NT*FD];   // teacher projections, fp16
__device__ __align__(16) uint4 g_wq[2][2][2][2048];  // [net][layer][hi/lo] swizzled bf16 chunks
__device__ int   g_keymap[KEYSPACE];   // 0 = empty; restored by k_fin each launch
__device__ int   g_matched[NS];
__device__ int   g_tidx[NS];
__device__ int   g_cnt;
__device__ float g_accum;
__device__ float g_bn_sum[2][FD];
__device__ float g_bn_sq[2][FD];

// ---------------- helpers ---------------------------------------------------------------
__device__ __forceinline__ uint32_t smem_to_u32(const void* p) {
    uint32_t a;
    asm("{ .reg .u64 t; cvta.to.shared.u64 t, %1; cvt.u32.u64 %0, t; }" : "=r"(a) : "l"(p));
    return a;
}
__device__ __forceinline__ void cp16(uint32_t s, const void* g) {
    asm volatile("cp.async.cg.shared.global [%0], [%1], 16;" :: "r"(s), "l"(g));
}
__device__ __forceinline__ void cp_commit_wait() {
    asm volatile("cp.async.commit_group;");
    asm volatile("cp.async.wait_group 0;");
}
__device__ __forceinline__ void ldm_x4(uint32_t* r, uint32_t addr) {
    asm volatile("ldmatrix.sync.aligned.m8n8.x4.shared.b16 {%0,%1,%2,%3}, [%4];"
        : "=r"(r[0]), "=r"(r[1]), "=r"(r[2]), "=r"(r[3]) : "r"(addr));
}
__device__ __forceinline__ void ldm_x2(uint32_t* r, uint32_t addr) {
    asm volatile("ldmatrix.sync.aligned.m8n8.x2.shared.b16 {%0,%1}, [%2];"
        : "=r"(r[0]), "=r"(r[1]) : "r"(addr));
}
__device__ __forceinline__ void mma_bf16(float* c, const uint32_t* a, const uint32_t* b) {
    asm volatile("mma.sync.aligned.m16n8k16.row.col.f32.bf16.bf16.f32 "
        "{%0,%1,%2,%3}, {%4,%5,%6,%7}, {%8,%9}, {%0,%1,%2,%3};"
        : "+f"(c[0]), "+f"(c[1]), "+f"(c[2]), "+f"(c[3])
        : "r"(a[0]), "r"(a[1]), "r"(a[2]), "r"(a[3]), "r"(b[0]), "r"(b[1]));
}
// fp16-accumulator MMA: D(half2 x2) = A*B + C
__device__ __forceinline__ void mma_f16acc(uint32_t* c, const uint32_t* a, const uint32_t* b) {
    asm volatile("mma.sync.aligned.m16n8k16.row.col.f16.f16.f16.f16 "
        "{%0,%1}, {%2,%3,%4,%5}, {%6,%7}, {%0,%1};"
        : "+r"(c[0]), "+r"(c[1])
        : "r"(a[0]), "r"(a[1]), "r"(a[2]), "r"(a[3]), "r"(b[0]), "r"(b[1]));
}
__device__ __forceinline__ float fexp(float x) {
    float y = x * 1.44269504088896340736f;
    float n = rintf(y);
    float t = (y - n) * 0.69314718055994530942f;
    float p = 1.0f/720.0f;
    p = fmaf(p, t, 1.0f/120.0f);
    p = fmaf(p, t, 1.0f/24.0f);
    p = fmaf(p, t, 1.0f/6.0f);
    p = fmaf(p, t, 0.5f);
    p = fmaf(p, t, 1.0f);
    p = fmaf(p, t, 1.0f);
    int ni = (int)n;
    return p * __int_as_float((ni + 127) << 23);
}
__device__ __forceinline__ uint32_t pack_hi(float a, float b) {
    __nv_bfloat16 h0 = __float2bfloat16(a), h1 = __float2bfloat16(b);
    return (uint32_t)__bfloat16_as_ushort(h0) | ((uint32_t)__bfloat16_as_ushort(h1) << 16);
}
__device__ __forceinline__ uint32_t pack_lo(float a, float b) {
    __nv_bfloat16 h0 = __float2bfloat16(a), h1 = __float2bfloat16(b);
    float r0 = a - __bfloat162float(h0), r1 = b - __bfloat162float(h1);
    __nv_bfloat16 l0 = __float2bfloat16(r0), l1 = __float2bfloat16(r1);
    return (uint32_t)__bfloat16_as_ushort(l0) | ((uint32_t)__bfloat16_as_ushort(l1) << 16);
}

// ---------------- prep: scatter keys + clears + coalesced weight transpose ---------------
// blocks 0..31: keymap scatter + clears. blocks 32..35: one (net,layer) weight transpose.
__global__ void k_prep(const int* __restrict__ tc,
                       const float* __restrict__ tw1, const float* __restrict__ tw2,
                       const float* __restrict__ sw1, const float* __restrict__ sw2) {
    __shared__ float ws[32*128];   // 16KB staging for transpose blocks
    int tid = threadIdx.x;

    if (blockIdx.x < 32) {
        int i = blockIdx.x * 256 + tid;
        int4 c = ((const int4*)tc)[i];
        int key = ((c.x * 64 + c.y) * 128 + c.z) * 128 + c.w;
        g_keymap[key] = i + 1;
        g_matched[i] = 0;
        if (i < 2*FD) {
            ((float*)g_bn_sum)[i] = 0.f;
            ((float*)g_bn_sq)[i]  = 0.f;
        }
        if (i == 0) { g_cnt = 0; g_accum = 0.f; }
        return;
    }

    int wb = blockIdx.x - 32;
    int net = wb >> 1, layer = wb & 1;
    const float* w = net ? (layer ? sw2 : sw1) : (layer ? tw2 : tw1);
    for (int kc = 0; kc < 4; kc++) {
        #pragma unroll
        for (int i = 0; i < 16; i++) ws[tid + i*256] = w[kc*4096 + tid + i*256];
        __syncthreads();
        #pragma unroll
        for (int it = 0; it < 2; it++) {
            int item = tid + it*256;
            int n = item >> 2, sub = item & 3;
            uint32_t hw4[4], lw4[4];
            #pragma unroll
            for (int q = 0; q < 4; q++) {
                float v0 = ws[(sub*8 + q*2    )*128 + n];
                float v1 = ws[(sub*8 + q*2 + 1)*128 + n];
                hw4[q] = pack_hi(v0, v1);
                lw4[q] = pack_lo(v0, v1);
            }
            int ch = kc*4 + sub;
            int idx = n*16 + (ch ^ (n & 7));
            g_wq[net][layer][0][idx] = make_uint4(hw4[0], hw4[1], hw4[2], hw4[3]);
            g_wq[net][layer][1][idx] = make_uint4(lw4[0], lw4[1], lw4[2], lw4[3]);
        }
        __syncthreads();
    }
}

// ---------------- fused 2-layer projection via HMMA hi/lo (+ distributed match) ----------
#define PJ_XH 0
#define PJ_XL 32768
#define PJ_W1H 65536
#define PJ_W1L 98304
#define PJ_W2H 131072
#define PJ_W2L 163840
#define PJ_BIAS 196608
#define PJ_CS 197632
#define PJ_CQ 198144
#define SM_PROJ 198656

__global__ __launch_bounds__(256) void k_projmma(
    const float* __restrict__ tf, const float* __restrict__ sf,
    const float* __restrict__ tb1, const float* __restrict__ tb2,
    const float* __restrict__ sb1, const float* __restrict__ sb2,
    const int* __restrict__ sco)
{
    extern __shared__ char smc[];
    uint32_t sb = smem_to_u32(smc);
    float* smf = (float*)smc;
    int net = blockIdx.z;
    const float* x  = net ? sf : tf;
    const float* b1 = net ? sb1 : tb1;
    const float* b2 = net ? sb2 : tb2;
    int tid = threadIdx.x;
    int r0 = blockIdx.x * 128;

    // distributed coordinate matching: 64 student rows per CTA (128 CTAs total)
    if (tid < 64) {
        int j0 = (net * 64 + blockIdx.x) * 64 + tid;
        int4 c = ((const int4*)sco)[j0];
        int key = ((c.x * 64 + c.y) * 128 + c.z) * 128 + c.w;
        int t = g_keymap[key] - 1;
        g_tidx[j0] = (t < 0) ? 0 : t;
        unsigned m = __ballot_sync(0xffffffffu, t >= 0);
        int base = 0;
        if ((tid & 31) == 0) base = atomicAdd(&g_cnt, __popc(m));
        base = __shfl_sync(0xffffffffu, base, 0);
        if (t >= 0) {
            int rank = __popc(m & ((1u << (tid & 31)) - 1u));
            g_matched[base + rank] = j0;
        }
    }

    // load X fp32 -> hi/lo bf16 swizzled smem
    #pragma unroll
    for (int it = 0; it < 8; it++) {
        int cidx = tid + it * 256;
        int row = cidx >> 4, ch = cidx & 15;
        const float4* src = (const float4*)(x + (size_t)(r0 + row) * FD + ch * 8);
        float4 f0 = src[0], f1 = src[1];
        uint4 hv, lv;
        hv.x = pack_hi(f0.x, f0.y); lv.x = pack_lo(f0.x, f0.y);
        hv.y = pack_hi(f0.z, f0.w); lv.y = pack_lo(f0.z, f0.w);
        hv.z = pack_hi(f1.x, f1.y); lv.z = pack_lo(f1.x, f1.y);
        hv.w = pack_hi(f1.z, f1.w); lv.w = pack_lo(f1.z, f1.w);
        uint32_t off = (uint32_t)row * 256 + (uint32_t)((ch ^ (row & 7)) << 4);
        *(uint4*)(smc + PJ_XH + off) = hv;
        *(uint4*)(smc + PJ_XL + off) = lv;
    }
    #pragma unroll
    for (int it = 0; it < 8; it++) {
        int cidx = tid + it * 256;
        ((uint4*)(smc + PJ_W1H))[cidx] = g_wq[net][0][0][cidx];
        ((uint4*)(smc + PJ_W1L))[cidx] = g_wq[net][0][1][cidx];
        ((uint4*)(smc + PJ_W2H))[cidx] = g_wq[net][1][0][cidx];
        ((uint4*)(smc + PJ_W2L))[cidx] = g_wq[net][1][1][cidx];
    }
    if (tid < 128) {
        smf[PJ_BIAS/4 + tid]       = b1[tid];
        smf[PJ_BIAS/4 + 128 + tid] = b2[tid];
        smf[PJ_CS/4 + tid] = 0.f;
        smf[PJ_CQ/4 + tid] = 0.f;
    }
    __syncthreads();

    int lane = tid & 31, wid = tid >> 5;
    int wm = wid >> 2, wn = wid & 3;
    int a_sub   = lane >> 3;
    int a_rowin = (lane & 7) + ((a_sub & 1) << 3);
    int a_cb    = a_sub >> 1;
    int b_rowin = lane & 7;
    int b_cb    = (lane >> 3) & 1;
    int g = lane >> 2, t = lane & 3;

    uint32_t aBase[4], bBase[4];
    int aM7[4], bM7[4];
    #pragma unroll
    for (int i = 0; i < 4; i++) {
        int row = wm * 64 + i * 16 + a_rowin;
        aBase[i] = sb + PJ_XH + row * 256;
        aM7[i] = row & 7;
        int rn = wn * 32 + i * 8 + b_rowin;
        bBase[i] = sb + rn * 256;
        bM7[i] = rn & 7;
    }

    float acc[4][4][4];

    // ---- layer 1 ----
    #pragma unroll
    for (int i = 0; i < 4; i++)
        #pragma unroll
        for (int j = 0; j < 4; j++)
            #pragma unroll
            for (int q = 0; q < 4; q++) acc[i][j][q] = 0.f;
    #pragma unroll
    for (int ks = 0; ks < 8; ks++) {
        int k2 = ks * 2;
        uint32_t aH[4][4], aL[4][4], bH[4][2], bL[4][2];
        #pragma unroll
        for (int i = 0; i < 4; i++) {
            uint32_t ad = aBase[i] + (((k2 + a_cb) ^ aM7[i]) << 4);
            ldm_x4(aH[i], ad);
            ldm_x4(aL[i], ad + 32768);
        }
        #pragma unroll
        for (int j = 0; j < 4; j++) {
            uint32_t bd = bBase[j] + PJ_W1H + (((k2 + b_cb) ^ bM7[j]) << 4);
            ldm_x2(bH[j], bd);
            ldm_x2(bL[j], bd + 32768);
        }
        #pragma unroll
        for (int i = 0; i < 4; i++)
            #pragma unroll
            for (int j = 0; j < 4; j++) {
                mma_bf16(acc[i][j], aH[i], bH[j]);
                mma_bf16(acc[i][j], aH[i], bL[j]);
                mma_bf16(acc[i][j], aL[i], bH[j]);
            }
    }
    __syncthreads();

    // bias + relu + re-split into XH/XL (now H1)
    #pragma unroll
    for (int i = 0; i < 4; i++) {
        #pragma unroll
        for (int j = 0; j < 4; j++) {
            int col0 = wn * 32 + j * 8 + t * 2;
            float bb0 = smf[PJ_BIAS/4 + col0], bb1 = smf[PJ_BIAS/4 + col0 + 1];
            float v0 = fmaxf(acc[i][j][0] + bb0, 0.f);
            float v1 = fmaxf(acc[i][j][1] + bb1, 0.f);
            float v2 = fmaxf(acc[i][j][2] + bb0, 0.f);
            float v3 = fmaxf(acc[i][j][3] + bb1, 0.f);
            int rl = wm * 64 + i * 16 + g, rh = rl + 8;
            uint32_t offl = rl * 256 + (((col0 >> 3) ^ (rl & 7)) << 4) + (col0 & 7) * 2;
            uint32_t offh = rh * 256 + (((col0 >> 3) ^ (rh & 7)) << 4) + (col0 & 7) * 2;
            *(uint32_t*)(smc + PJ_XH + offl) = pack_hi(v0, v1);
            *(uint32_t*)(smc + PJ_XL + offl) = pack_lo(v0, v1);
            *(uint32_t*)(smc + PJ_XH + offh) = pack_hi(v2, v3);
            *(uint32_t*)(smc + PJ_XL + offh) = pack_lo(v2, v3);
        }
    }
    __syncthreads();

    // ---- layer 2 ----
    #pragma unroll
    for (int i = 0; i < 4; i++)
        #pragma unroll
        for (int j = 0; j < 4; j++)
            #pragma unroll
            for (int q = 0; q < 4; q++) acc[i][j][q] = 0.f;
    #pragma unroll
    for (int ks = 0; ks < 8; ks++) {
        int k2 = ks * 2;
        uint32_t aH[4][4], aL[4][4], bH[4][2], bL[4][2];
        #pragma unroll
        for (int i = 0; i < 4; i++) {
            uint32_t ad = aBase[i] + (((k2 + a_cb) ^ aM7[i]) << 4);
            ldm_x4(aH[i], ad);
            ldm_x4(aL[i], ad + 32768);
        }
        #pragma unroll
        for (int j = 0; j < 4; j++) {
            uint32_t bd = bBase[j] + PJ_W2H + (((k2 + b_cb) ^ bM7[j]) << 4);
            ldm_x2(bH[j], bd);
            ldm_x2(bL[j], bd + 32768);
        }
        #pragma unroll
        for (int i = 0; i < 4; i++)
            #pragma unroll
            for (int j = 0; j < 4; j++) {
                mma_bf16(acc[i][j], aH[i], bH[j]);
                mma_bf16(acc[i][j], aH[i], bL[j]);
                mma_bf16(acc[i][j], aL[i], bH[j]);
            }
    }

    float* out = g_h2[net];
    #pragma unroll
    for (int j = 0; j < 4; j++) {
        int col0 = wn * 32 + j * 8 + t * 2;
        float bb0 = smf[PJ_BIAS/4 + 128 + col0], bb1 = smf[PJ_BIAS/4 + 128 + col0 + 1];
        float s0 = 0.f, q0 = 0.f, s1 = 0.f, q1 = 0.f;
        #pragma unroll
        for (int i = 0; i < 4; i++) {
            float v0 = acc[i][j][0] + bb0;
            float v1 = acc[i][j][1] + bb1;
            float v2 = acc[i][j][2] + bb0;
            float v3 = acc[i][j][3] + bb1;
            int rl = wm * 64 + i * 16 + g, rh = rl + 8;
            *(float2*)&out[(size_t)(r0 + rl) * FD + col0] = make_float2(v0, v1);
            *(float2*)&out[(size_t)(r0 + rh) * FD + col0] = make_float2(v2, v3);
            s0 += v0 + v2; q0 += v0*v0 + v2*v2;
            s1 += v1 + v3; q1 += v1*v1 + v3*v3;
        }
        atomicAdd(&smf[PJ_CS/4 + col0], s0);
        atomicAdd(&smf[PJ_CQ/4 + col0], q0);
        atomicAdd(&smf[PJ_CS/4 + col0 + 1], s1);
        atomicAdd(&smf[PJ_CQ/4 + col0 + 1], q1);
    }
    __syncthreads();
    if (tid < 128) {
        atomicAdd(&g_bn_sum[net][tid], smf[PJ_CS/4 + tid]);
        atomicAdd(&g_bn_sq[net][tid],  smf[PJ_CQ/4 + tid]);
    }
}

// ---------------- fused BNfinal + BN apply + L2 normalize + fp16 convert ------------------
__global__ void k_normsplit(const float* __restrict__ tg, const float* __restrict__ tbe,
                            const float* __restrict__ sg, const float* __restrict__ sbe) {
    int net = blockIdx.z;
    const float* h = g_h2[net];
    const float* gam = net ? sg : tg;
    const float* bet = net ? sbe : tbe;
    __half* dst = net ? g_Ah : g_Bh;
    int w = threadIdx.x >> 5, l = threadIdx.x & 31;
    int r = blockIdx.x * 8 + w;

    float4 su = *(const float4*)&g_bn_sum[net][l*4];
    float4 sq = *(const float4*)&g_bn_sq[net][l*4];
    float4 gm = *(const float4*)&gam[l*4];
    float4 bt = *(const float4*)&bet[l*4];
    float sc[4], sh[4];
    {
        float mu, var;
        mu = su.x*(1.f/8192.f); var = sq.x*(1.f/8192.f) - mu*mu;
        sc[0] = rsqrtf(var + BN_EPS) * gm.x; sh[0] = bt.x - mu * sc[0];
        mu = su.y*(1.f/8192.f); var = sq.y*(1.f/8192.f) - mu*mu;
        sc[1] = rsqrtf(var + BN_EPS) * gm.y; sh[1] = bt.y - mu * sc[1];
        mu = su.z*(1.f/8192.f); var = sq.z*(1.f/8192.f) - mu*mu;
        sc[2] = rsqrtf(var + BN_EPS) * gm.z; sh[2] = bt.z - mu * sc[2];
        mu = su.w*(1.f/8192.f); var = sq.w*(1.f/8192.f) - mu*mu;
        sc[3] = rsqrtf(var + BN_EPS) * gm.w; sh[3] = bt.w - mu * sc[3];
    }
    float4 v = *(const float4*)&h[(size_t)r*FD + l*4];
    float y[4];
    y[0] = fmaf(v.x, sc[0], sh[0]); y[1] = fmaf(v.y, sc[1], sh[1]);
    y[2] = fmaf(v.z, sc[2], sh[2]); y[3] = fmaf(v.w, sc[3], sh[3]);
    float ss = y[0]*y[0] + y[1]*y[1] + y[2]*y[2] + y[3]*y[3];
    #pragma unroll
    for (int o = 16; o > 0; o >>= 1) ss += __shfl_xor_sync(0xffffffffu, ss, o);
    float inv = rsqrtf(ss);
    __half2 p0 = __floats2half2_rn(y[0]*inv, y[1]*inv);
    __half2 p1 = __floats2half2_rn(y[2]*inv, y[3]*inv);
    uint2 pk = make_uint2(*(uint32_t*)&p0, *(uint32_t*)&p1);
    *(uint2*)&dst[(size_t)r*FD + l*4] = pk;
}

// ---------------- fp16 HMMA GEMM, fp16 accumulators, 3 CTA/SM (R12 config) ----------------
#define SM_GEMM 65536

__global__ __launch_bounds__(256, 3) void k_gemm() {
    if ((int)(blockIdx.y * 128) >= g_cnt) return;
    extern __shared__ char smc[];
    uint32_t sb = smem_to_u32(smc);
    int tid = threadIdx.x, lane = tid & 31, wid = tid >> 5;
    int wm = wid >> 2, wn = wid & 3;        // warp tile 64x32
    const int* mrow = &g_matched[blockIdx.y * 128];

    #pragma unroll
    for (int it = 0; it < 8; it++) {
        int idx = tid + it * 256;
        int row = idx >> 4, ch = idx & 15;
        uint32_t swz = (uint32_t)((ch & 8) | ((ch ^ row) & 7));
        uint32_t off = (uint32_t)row * 256 + (swz << 4);
        int ar = __ldg(&mrow[row]);
        cp16(sb + off,         (const char*)(g_Ah + (size_t)ar * FD) + ch * 16);
        cp16(sb + 32768 + off, (const char*)(g_Bh + (size_t)(blockIdx.x * 128 + row) * FD) + ch * 16);
    }
    cp_commit_wait();
    __syncthreads();

    int a_sub   = lane >> 3;
    int a_rowin = (lane & 7) + ((a_sub & 1) << 3);
    int a_cb    = a_sub >> 1;
    int b_rowin = lane & 7;
    int b_cb    = (lane >> 3) & 1;

    uint32_t aBase[4], bBase[4];
    int aM7[4], bM7[4];
    #pragma unroll
    for (int i = 0; i < 4; i++) {
        int row = wm * 64 + i * 16 + a_rowin;
        aBase[i] = sb + row * 256;
        aM7[i] = row & 7;
        int rn = wn * 32 + i * 8 + b_rowin;
        bBase[i] = sb + 32768 + rn * 256;
        bM7[i] = rn & 7;
    }

    uint32_t acc2[4][4][2];
    #pragma unroll
    for (int i = 0; i < 4; i++)
        #pragma unroll
        for (int j = 0; j < 4; j++) { acc2[i][j][0] = 0u; acc2[i][j][1] = 0u; }

    #pragma unroll
    for (int ks = 0; ks < 8; ks++) {
        int k2 = ks * 2;
        uint32_t aF[4][4], bF[4][2];
        #pragma unroll
        for (int i = 0; i < 4; i++) {
            int c = k2 + a_cb;
            uint32_t swz = (uint32_t)((c & 8) | ((c ^ aM7[i]) & 7));
            ldm_x4(aF[i], aBase[i] + (swz << 4));
        }
        #pragma unroll
        for (int j = 0; j < 4; j++) {
            int c = k2 + b_cb;
            uint32_t swz = (uint32_t)((c & 8) | ((c ^ bM7[j]) & 7));
            ldm_x2(bF[j], bBase[j] + (swz << 4));
        }
        #pragma unroll
        for (int i = 0; i < 4; i++)
            #pragma unroll
            for (int j = 0; j < 4; j++)
                mma_f16acc(acc2[i][j], aF[i], bF[j]);
    }

    // epilogue: half2 -> int16 quant, pack pairs, store
    int g = lane >> 2, t = lane & 3;
    size_t rowbase = (size_t)blockIdx.y * 128 + wm * 64 + g;
    int colbase = blockIdx.x * 128 + wn * 32 + t * 2;
    #pragma unroll
    for (int i = 0; i < 4; i++) {
        #pragma unroll
        for (int j = 0; j < 4; j++) {
            size_t r0 = (rowbase + i*16) * NT + colbase + j*8;
            __half2 h0 = *(__half2*)&acc2[i][j][0];
            __half2 h1 = *(__half2*)&acc2[i][j][1];
            int q0 = __float2int_rn(__low2float(h0)  * QSCALE);
            int q1 = __float2int_rn(__high2float(h0) * QSCALE);
            int q2 = __float2int_rn(__low2float(h1)  * QSCALE);
            int q3 = __float2int_rn(__high2float(h1) * QSCALE);
            *(uint32_t*)&g_simsq[r0]                 = (q0 & 0xFFFF) | (q1 << 16);
            *(uint32_t*)&g_simsq[r0 + (size_t)8*NT]  = (q2 & 0xFFFF) | (q3 << 16);
        }
    }
}

// ---------------- exact top-k + logsumexp: 2 rows per CTA, 256 threads each ---------------
__global__ __launch_bounds__(512) void k_select() {
    __shared__ int hist[8192];     // two 4096-bin hists, one per half
    __shared__ int wtot[16];
    __shared__ int wsuf[16];
    __shared__ float wz[16];
    __shared__ int h16[32];
    __shared__ int misc[4];
    int tid = threadIdx.x, lane = tid & 31;
    int half = tid >> 8, htid = tid & 255, hw = htid >> 5;
    int cnt = g_cnt;
    int r = blockIdx.x * 2 + half;
    bool active = (r < cnt);

    #pragma unroll
    for (int i = 0; i < 4; i++) ((int4*)hist)[tid + i*512] = make_int4(0,0,0,0);
    if (tid < 32) h16[tid] = 0;
    __syncthreads();

    // row in registers: 32 int16 per thread (16 packed words)
    uint32_t w[16];
    int* myh = hist + (half << 12);
    if (active) {
        const uint4* g4 = (const uint4*)(g_simsq + (size_t)r * NT);
        #pragma unroll
        for (int u = 0; u < 4; u++) {
            uint4 v = g4[htid + u*256];
            w[u*4+0] = v.x; w[u*4+1] = v.y; w[u*4+2] = v.z; w[u*4+3] = v.w;
        }
        #pragma unroll
        for (int i = 0; i < 16; i++) {
            int q0 = (int)(short)(w[i] & 0xFFFF);
            int q1 = (int)(short)(w[i] >> 16);
            atomicAdd(&myh[(q0 + 32768) >> 4], 1);
            atomicAdd(&myh[(q1 + 32768) >> 4], 1);
        }
    }
    __syncthreads();

    // per-half suffix scan: 16 bins per thread, 8 warps per half
    int cs = 0;
    #pragma unroll
    for (int i = 0; i < 16; i++) cs += myh[htid*16 + i];
    int x = cs;
    #pragma unroll
    for (int off = 1; off < 32; off <<= 1) {
        int yv = __shfl_down_sync(0xffffffffu, x, off);
        if (lane + off < 32) x += yv;
    }
    if (lane == 0) wtot[half*8 + hw] = x;
    __syncthreads();
    if (htid < 8) {
        int s = 0;
        for (int ww = htid + 1; ww < 8; ww++) s += wtot[half*8 + ww];
        wsuf[half*8 + htid] = s;
    }
    __syncthreads();
    int incl = x + wsuf[half*8 + hw];
    int excl = incl - cs;
    if (active && incl >= KSEL && excl < KSEL) {
        int cum = excl;
        for (int b = htid*16 + 15; b >= htid*16; b--) {
            cum += myh[b];
            if (cum >= KSEL) { misc[half*2] = b; misc[half*2+1] = KSEL - (cum - myh[b]); break; }
        }
    }
    __syncthreads();
    int B = misc[half*2], j = misc[half*2+1];
    int C = (B << 4) - 32768;

    // pass 2: exp over bins > B, tally boundary slots
    float z = 0.f;
    if (active) {
        #pragma unroll
        for (int i = 0; i < 16; i++) {
            int q0 = (int)(short)(w[i] & 0xFFFF);
            int q1 = (int)(short)(w[i] >> 16);
            int b0 = (q0 + 32768) >> 4;
            int b1 = (q1 + 32768) >> 4;
            if (b0 > B) z += fexp((float)(q0 - C) * INV2048);
            else if (b0 == B) atomicAdd(&h16[half*16 + ((q0 + 32768) & 15)], 1);
            if (b1 > B) z += fexp((float)(q1 - C) * INV2048);
            else if (b1 == B) atomicAdd(&h16[half*16 + ((q1 + 32768) & 15)], 1);
        }
    }
    #pragma unroll
    for (int o = 16; o > 0; o >>= 1) z += __shfl_xor_sync(0xffffffffu, z, o);
    if (lane == 0) wz[half*8 + hw] = z;
    __syncthreads();

    if (active && htid == 0) {
        float Z = 0.f;
        #pragma unroll
        for (int i = 0; i < 8; i++) Z += wz[half*8 + i];
        int need = j;
        for (int s = 15; s >= 0 && need > 0; s--) {
            int c = h16[half*16 + s];
            if (c == 0) continue;
            int take = min(c, need);
            int q = B*16 + s - 32768;
            Z += (float)take * fexp((float)(q - C) * INV2048);
            need -= take;
        }
        int srow = g_matched[r];
        int qpos = (int)((const short*)g_simsq)[(size_t)r * NT + g_tidx[srow]];
        Z += fexp((float)(qpos - C) * INV2048);
        float pp = logf(Z) + (float)(C - qpos) * INV2048;
        atomicAdd(&g_accum, pp);
    }
}

// ---------------- finalize + keymap restore -----------------------------------------------
__global__ void k_fin(const int* __restrict__ tc, float* out) {
    int i = blockIdx.x * 256 + threadIdx.x;
    int4 c = ((const int4*)tc)[i];
    int key = ((c.x * 64 + c.y) * 128 + c.z) * 128 + c.w;
    g_keymap[key] = 0;
    if (i == 0) {
        int cnt = g_cnt;
        float d = (cnt > 0) ? (float)cnt : 1.0f;
        out[0] = g_accum / d;
    }
}

// ---------------- launch ------------------------------------------------------------------
extern "C" void kernel_launch(void* const* d_in, const int* in_sizes, int n_in,
                              void* d_out, int out_size) {
    const float* tf = (const float*)d_in[0];
    const float* sf = (const float*)d_in[1];
    const float* t_w1 = (const float*)d_in[2];
    const float* t_b1 = (const float*)d_in[3];
    const float* t_w2 = (const float*)d_in[4];
    const float* t_b2 = (const float*)d_in[5];
    const float* t_g  = (const float*)d_in[6];
    const float* t_be = (const float*)d_in[7];
    const float* s_w1 = (const float*)d_in[8];
    const float* s_b1 = (const float*)d_in[9];
    const float* s_w2 = (const float*)d_in[10];
    const float* s_b2 = (const float*)d_in[11];
    const float* s_g  = (const float*)d_in[12];
    const float* s_be = (const float*)d_in[13];
    const int* tco = (const int*)d_in[14];
    const int* sco = (const int*)d_in[15];

    cudaFuncSetAttribute(k_projmma, cudaFuncAttributeMaxDynamicSharedMemorySize, SM_PROJ);
    cudaFuncSetAttribute(k_gemm,    cudaFuncAttributeMaxDynamicSharedMemorySize, SM_GEMM);

    k_prep<<<36, 256>>>(tco, t_w1, t_w2, s_w1, s_w2);           // 0
    k_projmma<<<dim3(64,1,2), 256, SM_PROJ>>>(tf, sf,           // 1 (+ distributed match)
        t_b1, t_b2, s_b1, s_b2, sco);
    k_normsplit<<<dim3(1024,1,2), 256>>>(t_g, t_be, s_g, s_be); // 2
    k_gemm<<<dim3(64, 64), 256, SM_GEMM>>>();                   // 3
    k_select<<<4096, 512>>>();                                  // 4
    k_fin<<<32, 256>>>(tco, (float*)d_out);                     // 5
}